// round 2
// baseline (speedup 1.0000x reference)
#include <cuda_runtime.h>

// Problem constants
constexpr int cB = 4;
constexpr int cT = 2048;
constexpr int cD = 1024;
constexpr int cM = cB * cT;   // 8192 rows for QKV projection

// Tile config (classic SGEMM 128x128x8, 256 threads, 8x8 per thread)
constexpr int BM = 128;
constexpr int BN = 128;
constexpr int BK = 8;
constexpr int TM = 8;
constexpr int TN = 8;

// Scratch (static device globals — no runtime allocation allowed)
__device__ float g_Q[(size_t)cM * cD];
__device__ float g_K[(size_t)cM * cD];
__device__ float g_V[(size_t)cM * cD];
__device__ float g_S[(size_t)cB * cT * cT];

// ---------------------------------------------------------------------------
// NT tile GEMM: C[m,n] = sum_k A[m*K + k] * Bm[n*K + k]
// Both operands are K-contiguous (row-major [M,K] and [N,K]).
// ---------------------------------------------------------------------------
__device__ __forceinline__ void sgemm_nt_tile(
    const float* __restrict__ A, const float* __restrict__ Bm,
    float* __restrict__ C, int N, int K, int m0, int n0, int kIters)
{
    __shared__ float As[BK][BM];
    __shared__ float Bs[BK][BN];

    const int tid     = threadIdx.x;        // 0..255
    const int loadRow = tid >> 1;           // 0..127
    const int loadCol = (tid & 1) << 2;     // 0 or 4
    const int ty      = tid >> 4;           // 0..15
    const int tx      = tid & 15;           // 0..15

    float acc[TM][TN];
#pragma unroll
    for (int i = 0; i < TM; i++)
#pragma unroll
        for (int j = 0; j < TN; j++) acc[i][j] = 0.0f;

    const float* Aptr = A + (size_t)(m0 + loadRow) * K + loadCol;
    const float* Bptr = Bm + (size_t)(n0 + loadRow) * K + loadCol;

    for (int kt = 0; kt < kIters; kt++) {
        float4 av = *(const float4*)Aptr;
        float4 bv = *(const float4*)Bptr;
        As[loadCol + 0][loadRow] = av.x;
        As[loadCol + 1][loadRow] = av.y;
        As[loadCol + 2][loadRow] = av.z;
        As[loadCol + 3][loadRow] = av.w;
        Bs[loadCol + 0][loadRow] = bv.x;
        Bs[loadCol + 1][loadRow] = bv.y;
        Bs[loadCol + 2][loadRow] = bv.z;
        Bs[loadCol + 3][loadRow] = bv.w;
        __syncthreads();

#pragma unroll
        for (int kk = 0; kk < BK; kk++) {
            float a[TM], b[TN];
#pragma unroll
            for (int i = 0; i < TM; i++) a[i] = As[kk][ty * TM + i];
#pragma unroll
            for (int j = 0; j < TN; j++) b[j] = Bs[kk][tx * TN + j];
#pragma unroll
            for (int i = 0; i < TM; i++)
#pragma unroll
                for (int j = 0; j < TN; j++) acc[i][j] += a[i] * b[j];
        }
        __syncthreads();
        Aptr += BK;
        Bptr += BK;
    }

#pragma unroll
    for (int i = 0; i < TM; i++) {
        float* Crow = C + (size_t)(m0 + ty * TM + i) * N + n0 + tx * TN;
        float4 v0 = make_float4(acc[i][0], acc[i][1], acc[i][2], acc[i][3]);
        float4 v1 = make_float4(acc[i][4], acc[i][5], acc[i][6], acc[i][7]);
        *(float4*)(Crow)     = v0;
        *(float4*)(Crow + 4) = v1;
    }
}

// ---------------------------------------------------------------------------
// NN tile GEMM: C[m,n] = sum_k A[m*K + k] * Bm[k*N + n]
// ---------------------------------------------------------------------------
__device__ __forceinline__ void sgemm_nn_tile(
    const float* __restrict__ A, const float* __restrict__ Bm,
    float* __restrict__ C, int N, int K, int m0, int n0, int kIters)
{
    __shared__ float As[BK][BM];
    __shared__ float Bs[BK][BN];

    const int tid  = threadIdx.x;
    const int aRow = tid >> 1;
    const int aCol = (tid & 1) << 2;
    const int bRow = tid >> 5;          // 0..7
    const int bCol = (tid & 31) << 2;   // 0..124
    const int ty   = tid >> 4;
    const int tx   = tid & 15;

    float acc[TM][TN];
#pragma unroll
    for (int i = 0; i < TM; i++)
#pragma unroll
        for (int j = 0; j < TN; j++) acc[i][j] = 0.0f;

    const float* Aptr = A + (size_t)(m0 + aRow) * K + aCol;
    const float* Bptr = Bm + (size_t)bRow * N + n0 + bCol;

    for (int kt = 0; kt < kIters; kt++) {
        float4 av = *(const float4*)Aptr;
        float4 bv = *(const float4*)Bptr;
        As[aCol + 0][aRow] = av.x;
        As[aCol + 1][aRow] = av.y;
        As[aCol + 2][aRow] = av.z;
        As[aCol + 3][aRow] = av.w;
        *(float4*)&Bs[bRow][bCol] = bv;
        __syncthreads();

#pragma unroll
        for (int kk = 0; kk < BK; kk++) {
            float a[TM], b[TN];
#pragma unroll
            for (int i = 0; i < TM; i++) a[i] = As[kk][ty * TM + i];
#pragma unroll
            for (int j = 0; j < TN; j++) b[j] = Bs[kk][tx * TN + j];
#pragma unroll
            for (int i = 0; i < TM; i++)
#pragma unroll
                for (int j = 0; j < TN; j++) acc[i][j] += a[i] * b[j];
        }
        __syncthreads();
        Aptr += BK;
        Bptr += (size_t)BK * N;
    }

#pragma unroll
    for (int i = 0; i < TM; i++) {
        float* Crow = C + (size_t)(m0 + ty * TM + i) * N + n0 + tx * TN;
        float4 v0 = make_float4(acc[i][0], acc[i][1], acc[i][2], acc[i][3]);
        float4 v1 = make_float4(acc[i][4], acc[i][5], acc[i][6], acc[i][7]);
        *(float4*)(Crow)     = v0;
        *(float4*)(Crow + 4) = v1;
    }
}

// ---------------------------------------------------------------------------
// Kernel 1: Q/K/V projections.  z selects weight + destination.
// out[m,n] = sum_k X[m,k] * W[n,k]   (torch Linear: x @ W.T)
// ---------------------------------------------------------------------------
__global__ __launch_bounds__(256) void qkv_kernel(
    const float* __restrict__ X,
    const float* __restrict__ Wq,
    const float* __restrict__ Wk,
    const float* __restrict__ Wv)
{
    const float* W;
    float* C;
    switch (blockIdx.z) {
        case 0:  W = Wq; C = g_Q; break;
        case 1:  W = Wk; C = g_K; break;
        default: W = Wv; C = g_V; break;
    }
    sgemm_nt_tile(X, W, C, cD, cD, blockIdx.y * BM, blockIdx.x * BN, cD / BK);
}

// ---------------------------------------------------------------------------
// Kernel 2: S = Q K^T (per batch), causal tile skipping.
// ---------------------------------------------------------------------------
__global__ __launch_bounds__(256) void scores_kernel()
{
    const int b  = blockIdx.z;
    const int m0 = blockIdx.y * BM;
    const int n0 = blockIdx.x * BN;
    if (n0 > m0 + BM - 1) return;   // entire tile above causal diagonal

    const float* Qb = g_Q + (size_t)b * cT * cD;
    const float* Kb = g_K + (size_t)b * cT * cD;
    float* Sb       = g_S + (size_t)b * cT * cT;
    sgemm_nt_tile(Qb, Kb, Sb, cT, cD, m0, n0, cD / BK);
}

// ---------------------------------------------------------------------------
// Kernel 3: row-wise causal softmax (scale 1/sqrt(1024) = 1/32), in place.
// Zero-fills row tail up to the 128-tile boundary so PV GEMM reads clean data.
// ---------------------------------------------------------------------------
__global__ __launch_bounds__(256) void softmax_kernel()
{
    const int q   = blockIdx.x;
    const int b   = blockIdx.y;
    const int tid = threadIdx.x;
    float* row    = g_S + (size_t)b * cT * cT + (size_t)q * cT;
    const int len = q + 1;

    __shared__ float red[256];

    // 1) max
    float m = -1e30f;
    for (int i = tid; i < len; i += 256) m = fmaxf(m, row[i]);
    red[tid] = m;
    __syncthreads();
    for (int s = 128; s > 0; s >>= 1) {
        if (tid < s) red[tid] = fmaxf(red[tid], red[tid + s]);
        __syncthreads();
    }
    m = red[0];
    __syncthreads();

    // 2) exp + sum  (scale applied inside the exp: softmax(score/32))
    const float scale = 0.03125f;  // 1/sqrt(1024)
    float sum = 0.0f;
    for (int i = tid; i < len; i += 256) {
        float e = __expf((row[i] - m) * scale);
        row[i] = e;
        sum += e;
    }
    red[tid] = sum;
    __syncthreads();
    for (int s = 128; s > 0; s >>= 1) {
        if (tid < s) red[tid] += red[tid + s];
        __syncthreads();
    }
    const float inv = 1.0f / red[0];
    __syncthreads();

    // 3) normalize
    for (int i = tid; i < len; i += 256) row[i] *= inv;

    // 4) zero tail up to this row's 128-tile boundary (PV GEMM reads it)
    const int end = ((q >> 7) + 1) << 7;
    for (int i = len + tid; i < end; i += 256) row[i] = 0.0f;
}

// ---------------------------------------------------------------------------
// Kernel 4: O = P V (per batch); K-loop truncated at tile's causal limit.
// ---------------------------------------------------------------------------
__global__ __launch_bounds__(256) void pv_kernel(float* __restrict__ out)
{
    const int b  = blockIdx.z;
    const int m0 = blockIdx.y * BM;
    const int n0 = blockIdx.x * BN;

    const float* Pb = g_S + (size_t)b * cT * cT;
    const float* Vb = g_V + (size_t)b * cT * cD;
    float* Ob       = out + (size_t)b * cT * cD;

    const int kIters = (m0 + BM) / BK;   // only k <= causal limit of this tile
    sgemm_nn_tile(Pb, Vb, Ob, cD, cT, m0, n0, kIters);
}

// ---------------------------------------------------------------------------
extern "C" void kernel_launch(void* const* d_in, const int* in_sizes, int n_in,
                              void* d_out, int out_size)
{
    const float* X  = (const float*)d_in[0];
    const float* Wq = (const float*)d_in[1];
    const float* Wk = (const float*)d_in[2];
    const float* Wv = (const float*)d_in[3];
    float* out      = (float*)d_out;

    dim3 blk(256);

    // 1) Q/K/V projections: grid (N/BN, M/BM, 3)
    qkv_kernel<<<dim3(cD / BN, cM / BM, 3), blk>>>(X, Wq, Wk, Wv);

    // 2) scores: grid (T/BN, T/BM, B) with causal skip inside
    scores_kernel<<<dim3(cT / BN, cT / BM, cB), blk>>>();

    // 3) softmax: one block per row
    softmax_kernel<<<dim3(cT, cB), blk>>>();

    // 4) O = P V
    pv_kernel<<<dim3(cD / BN, cT / BM, cB), blk>>>(out);
}

// round 5
// speedup vs baseline: 2.4990x; 2.4990x over previous
#include <cuda_runtime.h>
#include <cuda_bf16.h>
#include <cstdint>

using bf16 = __nv_bfloat16;

// Problem constants
constexpr int cB = 4;
constexpr int cT = 2048;
constexpr int cD = 1024;
constexpr int cM = cB * cT;   // 8192

// GEMM tile config: 128x128 CTA tile, BK=32 bf16, 8 warps of 64x32
constexpr int BKc = 32;
constexpr int ROW_PITCH_B = 80;                    // 32 bf16 (64B) padded to 80B
constexpr int MAT_BYTES = 128 * ROW_PITCH_B;       // 10240
constexpr int STAGE_BYTES = 4 * MAT_BYTES;         // Ahi,Alo,Bhi,Blo = 40960
constexpr int SMEM_DYN = 2 * STAGE_BYTES;          // 81920 double buffered

// ---------------------------------------------------------------------------
// Scratch (static device globals — no runtime allocation allowed)
// ---------------------------------------------------------------------------
__device__ __align__(256) bf16 g_Xhi[(size_t)cM * cD];
__device__ __align__(256) bf16 g_Xlo[(size_t)cM * cD];
__device__ __align__(256) bf16 g_Wqhi[(size_t)cD * cD];
__device__ __align__(256) bf16 g_Wqlo[(size_t)cD * cD];
__device__ __align__(256) bf16 g_Wkhi[(size_t)cD * cD];
__device__ __align__(256) bf16 g_Wklo[(size_t)cD * cD];
__device__ __align__(256) bf16 g_Wvhi[(size_t)cD * cD];
__device__ __align__(256) bf16 g_Wvlo[(size_t)cD * cD];
__device__ __align__(256) bf16 g_Qhi[(size_t)cM * cD];
__device__ __align__(256) bf16 g_Qlo[(size_t)cM * cD];
__device__ __align__(256) bf16 g_Khi[(size_t)cM * cD];
__device__ __align__(256) bf16 g_Klo[(size_t)cM * cD];
__device__ __align__(256) bf16 g_Vhi[(size_t)cM * cD];
__device__ __align__(256) bf16 g_Vlo[(size_t)cM * cD];
__device__ __align__(256) bf16 g_Vthi[(size_t)cB * cD * cT];  // [B, D, T]
__device__ __align__(256) bf16 g_Vtlo[(size_t)cB * cD * cT];
__device__ __align__(256) float g_S[(size_t)cB * cT * cT];
__device__ __align__(256) bf16 g_Phi[(size_t)cB * cT * cT];
__device__ __align__(256) bf16 g_Plo[(size_t)cB * cT * cT];

// ---------------------------------------------------------------------------
// PTX helpers (family-portable: cp.async, ldmatrix, mma.sync)
// ---------------------------------------------------------------------------
__device__ __forceinline__ uint32_t smem_u32(const void* p) {
    uint32_t a;
    asm("{ .reg .u64 t; cvta.to.shared.u64 t, %1; cvt.u32.u64 %0, t; }"
        : "=r"(a) : "l"(p));
    return a;
}

__device__ __forceinline__ void cp_async16(uint32_t dst, const void* src) {
    asm volatile("cp.async.cg.shared.global [%0], [%1], 16;"
                 :: "r"(dst), "l"(src) : "memory");
}
__device__ __forceinline__ void cp_commit() {
    asm volatile("cp.async.commit_group;" ::: "memory");
}
template <int N>
__device__ __forceinline__ void cp_wait() {
    asm volatile("cp.async.wait_group %0;" :: "n"(N) : "memory");
}

__device__ __forceinline__ void ldsm_x4(uint32_t* r, uint32_t addr) {
    asm volatile("ldmatrix.sync.aligned.m8n8.x4.shared.b16 {%0,%1,%2,%3}, [%4];"
                 : "=r"(r[0]), "=r"(r[1]), "=r"(r[2]), "=r"(r[3]) : "r"(addr));
}

__device__ __forceinline__ void mma16816(float* c, const uint32_t* a, const uint32_t* b) {
    asm volatile(
        "mma.sync.aligned.m16n8k16.row.col.f32.bf16.bf16.f32 "
        "{%0,%1,%2,%3}, {%4,%5,%6,%7}, {%8,%9}, {%0,%1,%2,%3};"
        : "+f"(c[0]), "+f"(c[1]), "+f"(c[2]), "+f"(c[3])
        : "r"(a[0]), "r"(a[1]), "r"(a[2]), "r"(a[3]), "r"(b[0]), "r"(b[1]));
}

// ---------------------------------------------------------------------------
// Core: 128x128 output tile, C = A * B^T, operands given as bf16 hi/lo splits.
// A: rows m0..m0+127 of [.., lda]; B: rows n0..n0+127; K = kIters*32.
// EPI 0: write fp32 C ; EPI 1: write bf16 split Chi/Clo.
// ---------------------------------------------------------------------------
template <int EPI>
__device__ __forceinline__ void gemm128(
    const bf16* __restrict__ Ahi, const bf16* __restrict__ Alo,
    const bf16* __restrict__ Bhi, const bf16* __restrict__ Blo,
    int lda, int kIters, int m0, int n0,
    float* __restrict__ C, bf16* __restrict__ Chi, bf16* __restrict__ Clo, int ldc)
{
    extern __shared__ char smem[];
    const int tid  = threadIdx.x;
    const int wid  = tid >> 5;
    const int lane = tid & 31;
    const int wm   = (wid & 1) * 64;   // warp tile m-origin
    const int wn   = (wid >> 1) * 32;  // warp tile n-origin
    const uint32_t sbase = smem_u32(smem);

    float acc[4][4][4];
#pragma unroll
    for (int i = 0; i < 4; i++)
#pragma unroll
        for (int j = 0; j < 4; j++)
#pragma unroll
            for (int r = 0; r < 4; r++) acc[i][j][r] = 0.0f;

    // ---- async stage loader: 2048 x 16B chunks (4 mats x 128 rows x 4 segs)
    auto load_stage = [&](int s) {
        const int k0 = s * BKc;
        const uint32_t dst0 = sbase + (uint32_t)((s & 1) * STAGE_BYTES);
#pragma unroll
        for (int i = 0; i < 8; i++) {
            const int c   = tid + i * 256;
            const int mat = c >> 9;
            const int cc  = c & 511;
            const int row = cc >> 2;
            const int seg = cc & 3;
            const bf16* src = (mat == 0) ? Ahi : (mat == 1) ? Alo
                            : (mat == 2) ? Bhi : Blo;
            const int r0 = (mat < 2) ? m0 : n0;
            cp_async16(dst0 + (uint32_t)(mat * MAT_BYTES + row * ROW_PITCH_B + seg * 16),
                       src + (size_t)(r0 + row) * lda + k0 + seg * 8);
        }
        cp_commit();
    };

    load_stage(0);

    const int r8 = lane & 7;
    const int q  = lane >> 3;

    for (int kt = 0; kt < kIters; kt++) {
        if (kt + 1 < kIters) { load_stage(kt + 1); cp_wait<1>(); }
        else                 { cp_wait<0>(); }
        __syncthreads();

        const uint32_t sb = sbase + (uint32_t)((kt & 1) * STAGE_BYTES);
#pragma unroll
        for (int kh = 0; kh < 2; kh++) {
            const int k0 = kh * 16;
            // A fragments (hi & lo): 4 m-tiles of 16
            uint32_t ah[4][4], al[4][4];
#pragma unroll
            for (int mt = 0; mt < 4; mt++) {
                const uint32_t off = (uint32_t)(
                    (wm + mt * 16 + r8 + ((q & 1) << 3)) * ROW_PITCH_B +
                    (k0 + ((q >> 1) << 3)) * 2);
                ldsm_x4(ah[mt], sb + off);                       // Ahi at mat 0
                ldsm_x4(al[mt], sb + MAT_BYTES + off);           // Alo at mat 1
            }
            // B fragments (hi & lo): 4 n-tiles of 8, loaded as 2 x4 each
            uint32_t bh[4][2], bl[4][2];
#pragma unroll
            for (int np = 0; np < 2; np++) {
                const uint32_t off = (uint32_t)(
                    (wn + np * 16 + r8 + ((q >> 1) << 3)) * ROW_PITCH_B +
                    (k0 + ((q & 1) << 3)) * 2);
                uint32_t t[4];
                ldsm_x4(t, sb + 2 * MAT_BYTES + off);            // Bhi at mat 2
                bh[np * 2 + 0][0] = t[0]; bh[np * 2 + 0][1] = t[1];
                bh[np * 2 + 1][0] = t[2]; bh[np * 2 + 1][1] = t[3];
                ldsm_x4(t, sb + 3 * MAT_BYTES + off);            // Blo at mat 3
                bl[np * 2 + 0][0] = t[0]; bl[np * 2 + 0][1] = t[1];
                bl[np * 2 + 1][0] = t[2]; bl[np * 2 + 1][1] = t[3];
            }
            // 3-term split MMA: hi*hi + hi*lo + lo*hi
#pragma unroll
            for (int mt = 0; mt < 4; mt++)
#pragma unroll
                for (int nt = 0; nt < 4; nt++) {
                    mma16816(acc[mt][nt], ah[mt], bh[nt]);
                    mma16816(acc[mt][nt], ah[mt], bl[nt]);
                    mma16816(acc[mt][nt], al[mt], bh[nt]);
                }
        }
        __syncthreads();
    }

    // ---- epilogue ----
    const int er = lane >> 2;          // 0..7
    const int ec = (lane & 3) * 2;     // 0,2,4,6
#pragma unroll
    for (int mt = 0; mt < 4; mt++) {
#pragma unroll
        for (int half = 0; half < 2; half++) {
            const int gr = m0 + wm + mt * 16 + er + half * 8;
#pragma unroll
            for (int nt = 0; nt < 4; nt++) {
                const float v0 = acc[mt][nt][half * 2 + 0];
                const float v1 = acc[mt][nt][half * 2 + 1];
                const int gc = n0 + wn + nt * 8 + ec;
                if (EPI == 0) {
                    float2 v = make_float2(v0, v1);
                    *(float2*)(C + (size_t)gr * ldc + gc) = v;
                } else {
                    bf16 h0 = __float2bfloat16(v0);
                    bf16 h1 = __float2bfloat16(v1);
                    bf16 l0 = __float2bfloat16(v0 - __bfloat162float(h0));
                    bf16 l1 = __float2bfloat16(v1 - __bfloat162float(h1));
                    __nv_bfloat162 hh; hh.x = h0; hh.y = h1;
                    __nv_bfloat162 ll; ll.x = l0; ll.y = l1;
                    *(__nv_bfloat162*)(Chi + (size_t)gr * ldc + gc) = hh;
                    *(__nv_bfloat162*)(Clo + (size_t)gr * ldc + gc) = ll;
                }
            }
        }
    }
}

// ---------------------------------------------------------------------------
// Kernels
// ---------------------------------------------------------------------------
__global__ void convert_split_kernel(const float* __restrict__ in,
                                     bf16* __restrict__ hi, bf16* __restrict__ lo, int n)
{
    int i = blockIdx.x * 256 + threadIdx.x;
    if (i < n) {
        float x = in[i];
        bf16 h = __float2bfloat16(x);
        hi[i] = h;
        lo[i] = __float2bfloat16(x - __bfloat162float(h));
    }
}

__global__ __launch_bounds__(256, 1) void qkv_gemm_kernel()
{
    const int z = blockIdx.z;
    const bf16 *bh, *bl;
    bf16 *ch, *cl;
    if (z == 0)      { bh = g_Wqhi; bl = g_Wqlo; ch = g_Qhi; cl = g_Qlo; }
    else if (z == 1) { bh = g_Wkhi; bl = g_Wklo; ch = g_Khi; cl = g_Klo; }
    else             { bh = g_Wvhi; bl = g_Wvlo; ch = g_Vhi; cl = g_Vlo; }
    gemm128<1>(g_Xhi, g_Xlo, bh, bl, cD, cD / BKc,
               blockIdx.y * 128, blockIdx.x * 128, nullptr, ch, cl, cD);
}

// V [T, D] -> Vt [D, T] per batch, hi+lo
__global__ void transpose_kernel()
{
    __shared__ bf16 t[32][33];
    const int z = blockIdx.z;
    const int b = z >> 1, h = z & 1;
    const bf16* in = (h ? g_Vlo : g_Vhi) + (size_t)b * cT * cD;
    bf16* out      = (h ? g_Vtlo : g_Vthi) + (size_t)b * cD * cT;
    const int d0 = blockIdx.x * 32;
    const int t0 = blockIdx.y * 32;
    const int tx = threadIdx.x, ty = threadIdx.y;  // 32 x 8
#pragma unroll
    for (int j = 0; j < 32; j += 8)
        t[ty + j][tx] = in[(size_t)(t0 + ty + j) * cD + d0 + tx];
    __syncthreads();
#pragma unroll
    for (int j = 0; j < 32; j += 8)
        out[(size_t)(d0 + ty + j) * cT + t0 + tx] = t[tx][ty + j];
}

__global__ __launch_bounds__(256, 1) void scores_gemm_kernel()
{
    const int b  = blockIdx.z;
    const int m0 = blockIdx.y * 128;
    const int n0 = blockIdx.x * 128;
    if (n0 > m0) return;  // tile fully above causal diagonal
    const size_t off = (size_t)b * cT * cD;
    gemm128<0>(g_Qhi + off, g_Qlo + off, g_Khi + off, g_Klo + off,
               cD, cD / BKc, m0, n0,
               g_S + (size_t)b * cT * cT, nullptr, nullptr, cT);
}

// softmax row -> bf16 split P, zero-filled to the row's 128 boundary
__global__ __launch_bounds__(256) void softmax_split_kernel()
{
    const int q   = blockIdx.x;
    const int b   = blockIdx.y;
    const int tid = threadIdx.x;
    const size_t roff = (size_t)b * cT * cT + (size_t)q * cT;
    float* row = g_S + roff;
    bf16*  ph  = g_Phi + roff;
    bf16*  pl  = g_Plo + roff;
    const int len = q + 1;

    __shared__ float red[256];

    float m = -1e30f;
    for (int i = tid; i < len; i += 256) m = fmaxf(m, row[i]);
    red[tid] = m;
    __syncthreads();
    for (int s = 128; s > 0; s >>= 1) {
        if (tid < s) red[tid] = fmaxf(red[tid], red[tid + s]);
        __syncthreads();
    }
    m = red[0];
    __syncthreads();

    const float scale = 0.03125f;  // 1/sqrt(1024)
    float sum = 0.0f;
    for (int i = tid; i < len; i += 256) {
        float e = __expf((row[i] - m) * scale);
        row[i] = e;
        sum += e;
    }
    red[tid] = sum;
    __syncthreads();
    for (int s = 128; s > 0; s >>= 1) {
        if (tid < s) red[tid] += red[tid + s];
        __syncthreads();
    }
    const float inv = 1.0f / red[0];
    __syncthreads();

    for (int i = tid; i < len; i += 256) {
        float v = row[i] * inv;
        bf16 h = __float2bfloat16(v);
        ph[i] = h;
        pl[i] = __float2bfloat16(v - __bfloat162float(h));
    }
    const int end = ((q >> 7) + 1) << 7;
    const bf16 z = __float2bfloat16(0.0f);
    for (int i = len + tid; i < end; i += 256) {
        ph[i] = z;
        pl[i] = z;
    }
}

__global__ __launch_bounds__(256, 1) void pv_gemm_kernel(float* __restrict__ out)
{
    const int b  = blockIdx.z;
    const int m0 = blockIdx.y * 128;
    const int n0 = blockIdx.x * 128;
    const int kIters = (m0 + 128) / BKc;   // causal truncation
    const size_t poff = (size_t)b * cT * cT;
    const size_t voff = (size_t)b * cD * cT;
    gemm128<0>(g_Phi + poff, g_Plo + poff, g_Vthi + voff, g_Vtlo + voff,
               cT, kIters, m0, n0,
               out + (size_t)b * cT * cD, nullptr, nullptr, cD);
}

// ---------------------------------------------------------------------------
extern "C" void kernel_launch(void* const* d_in, const int* in_sizes, int n_in,
                              void* d_out, int out_size)
{
    const float* X  = (const float*)d_in[0];
    const float* Wq = (const float*)d_in[1];
    const float* Wk = (const float*)d_in[2];
    const float* Wv = (const float*)d_in[3];
    float* out      = (float*)d_out;

    cudaFuncSetAttribute(qkv_gemm_kernel,    cudaFuncAttributeMaxDynamicSharedMemorySize, SMEM_DYN);
    cudaFuncSetAttribute(scores_gemm_kernel, cudaFuncAttributeMaxDynamicSharedMemorySize, SMEM_DYN);
    cudaFuncSetAttribute(pv_gemm_kernel,     cudaFuncAttributeMaxDynamicSharedMemorySize, SMEM_DYN);

    // 1) bf16 hi/lo splits of inputs
    bf16 *xh, *xl, *wqh, *wql, *wkh, *wkl, *wvh, *wvl;
    cudaGetSymbolAddress((void**)&xh,  g_Xhi);  cudaGetSymbolAddress((void**)&xl,  g_Xlo);
    cudaGetSymbolAddress((void**)&wqh, g_Wqhi); cudaGetSymbolAddress((void**)&wql, g_Wqlo);
    cudaGetSymbolAddress((void**)&wkh, g_Wkhi); cudaGetSymbolAddress((void**)&wkl, g_Wklo);
    cudaGetSymbolAddress((void**)&wvh, g_Wvhi); cudaGetSymbolAddress((void**)&wvl, g_Wvlo);

    const int nX = cM * cD, nW = cD * cD;
    convert_split_kernel<<<(nX + 255) / 256, 256>>>(X,  xh,  xl,  nX);
    convert_split_kernel<<<(nW + 255) / 256, 256>>>(Wq, wqh, wql, nW);
    convert_split_kernel<<<(nW + 255) / 256, 256>>>(Wk, wkh, wkl, nW);
    convert_split_kernel<<<(nW + 255) / 256, 256>>>(Wv, wvh, wvl, nW);

    // 2) QKV projections (HMMA), epilogue re-splits to bf16 pairs
    qkv_gemm_kernel<<<dim3(cD / 128, cM / 128, 3), 256, SMEM_DYN>>>();

    // 3) V -> V^T per batch (hi+lo)
    transpose_kernel<<<dim3(cD / 32, cT / 32, cB * 2), dim3(32, 8)>>>();

    // 4) S = Q K^T, causal tiles only
    scores_gemm_kernel<<<dim3(cT / 128, cT / 128, cB), 256, SMEM_DYN>>>();

    // 5) softmax -> bf16 split P (tail-zeroed)
    softmax_split_kernel<<<dim3(cT, cB), 256>>>();

    // 6) O = P V
    pv_gemm_kernel<<<dim3(cD / 128, cT / 128, cB), 256, SMEM_DYN>>>(out);
}

// round 8
// speedup vs baseline: 3.6771x; 1.4714x over previous
#include <cuda_runtime.h>
#include <cstdint>

// Problem constants
constexpr int cB = 4;
constexpr int cT = 2048;
constexpr int cD = 1024;
constexpr int cM = cB * cT;   // 8192

// GEMM tile config: 128x128 CTA tile, BK=32 fp32(tf32), 8 warps of 64x32
constexpr int BKc   = 32;
constexpr int PITCH = 144;                 // 32 fp32 (128B) padded to 144B
constexpr int MATB  = 128 * PITCH;         // 18432
constexpr int STAGEB = 2 * MATB;           // A + B = 36864
constexpr int SMEM_DYN = 2 * STAGEB;       // 73728, double buffered

// ---------------------------------------------------------------------------
// Scratch (static device globals — no runtime allocation allowed)
// ---------------------------------------------------------------------------
__device__ __align__(256) float g_X [(size_t)cM * cD];
__device__ __align__(256) float g_Wq[(size_t)cD * cD];
__device__ __align__(256) float g_Wk[(size_t)cD * cD];
__device__ __align__(256) float g_Wv[(size_t)cD * cD];
__device__ __align__(256) float g_Q [(size_t)cM * cD];
__device__ __align__(256) float g_K [(size_t)cM * cD];
__device__ __align__(256) float g_V [(size_t)cM * cD];
__device__ __align__(256) float g_Vt[(size_t)cB * cD * cT];  // [B, D, T]
__device__ __align__(256) float g_S [(size_t)cB * cT * cT];  // scores, then P in place

// ---------------------------------------------------------------------------
// PTX helpers (family-portable: cp.async, ldmatrix, mma.sync tf32)
// ---------------------------------------------------------------------------
__device__ __forceinline__ uint32_t smem_u32(const void* p) {
    uint32_t a;
    asm("{ .reg .u64 t; cvta.to.shared.u64 t, %1; cvt.u32.u64 %0, t; }"
        : "=r"(a) : "l"(p));
    return a;
}

__device__ __forceinline__ void cp_async16(uint32_t dst, const void* src) {
    asm volatile("cp.async.cg.shared.global [%0], [%1], 16;"
                 :: "r"(dst), "l"(src) : "memory");
}
__device__ __forceinline__ void cp_commit() {
    asm volatile("cp.async.commit_group;" ::: "memory");
}
template <int N>
__device__ __forceinline__ void cp_wait() {
    asm volatile("cp.async.wait_group %0;" :: "n"(N) : "memory");
}

__device__ __forceinline__ void ldsm_x4(uint32_t* r, uint32_t addr) {
    asm volatile("ldmatrix.sync.aligned.m8n8.x4.shared.b16 {%0,%1,%2,%3}, [%4];"
                 : "=r"(r[0]), "=r"(r[1]), "=r"(r[2]), "=r"(r[3]) : "r"(addr));
}

__device__ __forceinline__ void mma_tf32(float* c, const uint32_t* a, const uint32_t* b) {
    asm volatile(
        "mma.sync.aligned.m16n8k8.row.col.f32.tf32.tf32.f32 "
        "{%0,%1,%2,%3}, {%4,%5,%6,%7}, {%8,%9}, {%0,%1,%2,%3};"
        : "+f"(c[0]), "+f"(c[1]), "+f"(c[2]), "+f"(c[3])
        : "r"(a[0]), "r"(a[1]), "r"(a[2]), "r"(a[3]), "r"(b[0]), "r"(b[1]));
}

// Round-to-nearest tf32 (unbiased — truncation would bias dot products ~1e-3)
__device__ __forceinline__ float to_tf32(float x) {
    uint32_t r;
    asm("cvt.rna.tf32.f32 %0, %1;" : "=r"(r) : "f"(x));
    return __uint_as_float(r);
}

// ---------------------------------------------------------------------------
// Core: 128x128 output tile, C = A * B^T, fp32 operands pre-rounded to tf32.
// A: rows m0..m0+127 of [.., lda]; B: rows n0..n0+127 of [.., lda]; K = kIters*32.
// ROUND: apply tf32 rounding to C on store (for Q/K/V feeding later GEMMs).
// ---------------------------------------------------------------------------
template <int ROUND>
__device__ __forceinline__ void gemm128_tf32(
    const float* __restrict__ A, const float* __restrict__ B,
    int lda, int kIters, int m0, int n0,
    float* __restrict__ C, int ldc)
{
    extern __shared__ char smem[];
    const int tid  = threadIdx.x;
    const int wid  = tid >> 5;
    const int lane = tid & 31;
    const int wm   = (wid & 1) * 64;   // warp tile m-origin
    const int wn   = (wid >> 1) * 32;  // warp tile n-origin
    const uint32_t sbase = smem_u32(smem);

    float acc[4][4][4];
#pragma unroll
    for (int i = 0; i < 4; i++)
#pragma unroll
        for (int j = 0; j < 4; j++)
#pragma unroll
            for (int r = 0; r < 4; r++) acc[i][j][r] = 0.0f;

    // ---- async stage loader: 2 mats x 128 rows x 8 x 16B chunks = 2048
    auto load_stage = [&](int s) {
        const int k0 = s * BKc;
        const uint32_t dst0 = sbase + (uint32_t)((s & 1) * STAGEB);
#pragma unroll
        for (int i = 0; i < 8; i++) {
            const int c   = tid + i * 256;   // 0..2047
            const int mat = c >> 10;
            const int cc  = c & 1023;
            const int row = cc >> 3;
            const int seg = cc & 7;
            const float* src = mat ? B : A;
            const int r0 = mat ? n0 : m0;
            cp_async16(dst0 + (uint32_t)(mat * MATB + row * PITCH + seg * 16),
                       src + (size_t)(r0 + row) * lda + k0 + seg * 4);
        }
        cp_commit();
    };

    load_stage(0);

    // ldmatrix lane->address: quad q selects (row+8?, col+4?) sub-tile
    const int q  = lane >> 3;
    const int r8 = lane & 7;
    const uint32_t a_off = (uint32_t)((wm + (q & 1) * 8 + r8) * PITCH + (q >> 1) * 16);
    const uint32_t b_off = (uint32_t)((wn + (q & 1) * 8 + r8) * PITCH + (q >> 1) * 16)
                           + (uint32_t)MATB;

    for (int kt = 0; kt < kIters; kt++) {
        if (kt + 1 < kIters) { load_stage(kt + 1); cp_wait<1>(); }
        else                 { cp_wait<0>(); }
        __syncthreads();

        const uint32_t sb = sbase + (uint32_t)((kt & 1) * STAGEB);
#pragma unroll
        for (int kh = 0; kh < 4; kh++) {           // 4 x k8 per stage
            uint32_t a[4][4], b[4][2];
#pragma unroll
            for (int mt = 0; mt < 4; mt++)
                ldsm_x4(a[mt], sb + a_off + (uint32_t)(mt * 16 * PITCH + kh * 32));
#pragma unroll
            for (int np = 0; np < 2; np++) {
                uint32_t t[4];
                ldsm_x4(t, sb + b_off + (uint32_t)(np * 16 * PITCH + kh * 32));
                b[2 * np + 0][0] = t[0]; b[2 * np + 1][0] = t[1];
                b[2 * np + 0][1] = t[2]; b[2 * np + 1][1] = t[3];
            }
#pragma unroll
            for (int mt = 0; mt < 4; mt++)
#pragma unroll
                for (int nt = 0; nt < 4; nt++)
                    mma_tf32(acc[mt][nt], a[mt], b[nt]);
        }
        __syncthreads();
    }

    // ---- epilogue ----
    const int er = lane >> 2;          // 0..7
    const int ec = (lane & 3) * 2;     // 0,2,4,6
#pragma unroll
    for (int mt = 0; mt < 4; mt++) {
#pragma unroll
        for (int half = 0; half < 2; half++) {
            const int gr = m0 + wm + mt * 16 + er + half * 8;
#pragma unroll
            for (int nt = 0; nt < 4; nt++) {
                float v0 = acc[mt][nt][half * 2 + 0];
                float v1 = acc[mt][nt][half * 2 + 1];
                if (ROUND) { v0 = to_tf32(v0); v1 = to_tf32(v1); }
                const int gc = n0 + wn + nt * 8 + ec;
                *(float2*)(C + (size_t)gr * ldc + gc) = make_float2(v0, v1);
            }
        }
    }
}

// ---------------------------------------------------------------------------
// Kernels
// ---------------------------------------------------------------------------
__global__ void round_tf32_kernel(const float* __restrict__ in,
                                  float* __restrict__ out, int n)
{
    int i = (blockIdx.x * 256 + threadIdx.x) * 4;
    if (i < n) {
        float4 v = *(const float4*)(in + i);
        v.x = to_tf32(v.x); v.y = to_tf32(v.y);
        v.z = to_tf32(v.z); v.w = to_tf32(v.w);
        *(float4*)(out + i) = v;
    }
}

__global__ __launch_bounds__(256, 2) void qkv_gemm_kernel()
{
    const int z = blockIdx.z;
    const float* W;
    float* C;
    if (z == 0)      { W = g_Wq; C = g_Q; }
    else if (z == 1) { W = g_Wk; C = g_K; }
    else             { W = g_Wv; C = g_V; }
    gemm128_tf32<1>(g_X, W, cD, cD / BKc,
                    blockIdx.y * 128, blockIdx.x * 128, C, cD);
}

// V [T, D] -> Vt [D, T] per batch (already tf32-rounded values)
__global__ void transpose_kernel()
{
    __shared__ float t[32][33];
    const int b = blockIdx.z;
    const float* in = g_V + (size_t)b * cT * cD;
    float* out      = g_Vt + (size_t)b * cD * cT;
    const int d0 = blockIdx.x * 32;
    const int t0 = blockIdx.y * 32;
    const int tx = threadIdx.x, ty = threadIdx.y;  // 32 x 8
#pragma unroll
    for (int j = 0; j < 32; j += 8)
        t[ty + j][tx] = in[(size_t)(t0 + ty + j) * cD + d0 + tx];
    __syncthreads();
#pragma unroll
    for (int j = 0; j < 32; j += 8)
        out[(size_t)(d0 + ty + j) * cT + t0 + tx] = t[tx][ty + j];
}

__global__ __launch_bounds__(256, 2) void scores_gemm_kernel()
{
    const int b  = blockIdx.z;
    const int m0 = blockIdx.y * 128;
    const int n0 = blockIdx.x * 128;
    if (n0 > m0) return;  // tile fully above causal diagonal
    const size_t off = (size_t)b * cT * cD;
    gemm128_tf32<0>(g_Q + off, g_K + off, cD, cD / BKc, m0, n0,
                    g_S + (size_t)b * cT * cT, cT);
}

// softmax row in place -> tf32-rounded P, zero-filled to the row's 128 boundary
__global__ __launch_bounds__(256) void softmax_kernel()
{
    const int q   = blockIdx.x;
    const int b   = blockIdx.y;
    const int tid = threadIdx.x;
    float* row    = g_S + (size_t)b * cT * cT + (size_t)q * cT;
    const int len = q + 1;

    __shared__ float red[256];

    float m = -1e30f;
    for (int i = tid; i < len; i += 256) m = fmaxf(m, row[i]);
    red[tid] = m;
    __syncthreads();
    for (int s = 128; s > 0; s >>= 1) {
        if (tid < s) red[tid] = fmaxf(red[tid], red[tid + s]);
        __syncthreads();
    }
    m = red[0];
    __syncthreads();

    const float scale = 0.03125f;  // 1/sqrt(1024)
    float sum = 0.0f;
    for (int i = tid; i < len; i += 256) {
        float e = __expf((row[i] - m) * scale);
        row[i] = e;
        sum += e;
    }
    red[tid] = sum;
    __syncthreads();
    for (int s = 128; s > 0; s >>= 1) {
        if (tid < s) red[tid] += red[tid + s];
        __syncthreads();
    }
    const float inv = 1.0f / red[0];
    __syncthreads();

    for (int i = tid; i < len; i += 256)
        row[i] = to_tf32(row[i] * inv);

    const int end = ((q >> 7) + 1) << 7;
    for (int i = len + tid; i < end; i += 256) row[i] = 0.0f;
}

__global__ __launch_bounds__(256, 2) void pv_gemm_kernel(float* __restrict__ out)
{
    const int b  = blockIdx.z;
    const int m0 = blockIdx.y * 128;
    const int n0 = blockIdx.x * 128;
    const int kIters = (m0 + 128) / BKc;   // causal truncation
    gemm128_tf32<0>(g_S + (size_t)b * cT * cT, g_Vt + (size_t)b * cD * cT,
                    cT, kIters, m0, n0,
                    out + (size_t)b * cT * cD, cD);
}

// ---------------------------------------------------------------------------
extern "C" void kernel_launch(void* const* d_in, const int* in_sizes, int n_in,
                              void* d_out, int out_size)
{
    const float* X  = (const float*)d_in[0];
    const float* Wq = (const float*)d_in[1];
    const float* Wk = (const float*)d_in[2];
    const float* Wv = (const float*)d_in[3];
    float* out      = (float*)d_out;

    cudaFuncSetAttribute(qkv_gemm_kernel,    cudaFuncAttributeMaxDynamicSharedMemorySize, SMEM_DYN);
    cudaFuncSetAttribute(scores_gemm_kernel, cudaFuncAttributeMaxDynamicSharedMemorySize, SMEM_DYN);
    cudaFuncSetAttribute(pv_gemm_kernel,     cudaFuncAttributeMaxDynamicSharedMemorySize, SMEM_DYN);

    float *xp, *wqp, *wkp, *wvp;
    cudaGetSymbolAddress((void**)&xp,  g_X);
    cudaGetSymbolAddress((void**)&wqp, g_Wq);
    cudaGetSymbolAddress((void**)&wkp, g_Wk);
    cudaGetSymbolAddress((void**)&wvp, g_Wv);

    const int nX = cM * cD, nW = cD * cD;

    // 1) round inputs to tf32 (rna — unbiased)
    round_tf32_kernel<<<(nX / 4 + 255) / 256, 256>>>(X,  xp,  nX);
    round_tf32_kernel<<<(nW / 4 + 255) / 256, 256>>>(Wq, wqp, nW);
    round_tf32_kernel<<<(nW / 4 + 255) / 256, 256>>>(Wk, wkp, nW);
    round_tf32_kernel<<<(nW / 4 + 255) / 256, 256>>>(Wv, wvp, nW);

    // 2) QKV projections (tf32 HMMA), outputs tf32-rounded
    qkv_gemm_kernel<<<dim3(cD / 128, cM / 128, 3), 256, SMEM_DYN>>>();

    // 3) V -> V^T per batch
    transpose_kernel<<<dim3(cD / 32, cT / 32, cB), dim3(32, 8)>>>();

    // 4) S = Q K^T, causal tiles only
    scores_gemm_kernel<<<dim3(cT / 128, cT / 128, cB), 256, SMEM_DYN>>>();

    // 5) softmax in place -> tf32-rounded P (tail-zeroed)
    softmax_kernel<<<dim3(cT, cB), 256>>>();

    // 6) O = P V
    pv_gemm_kernel<<<dim3(cD / 128, cT / 128, cB), 256, SMEM_DYN>>>(out);
}

// round 14
// speedup vs baseline: 3.6879x; 1.0029x over previous
#include <cuda_runtime.h>
#include <cstdint>

// Problem constants
constexpr int cB = 4;
constexpr int cT = 2048;
constexpr int cD = 1024;
constexpr int cM = cB * cT;   // 8192

// GEMM tile config: 128x128 CTA tile, BK=32 fp32(tf32), 8 warps of 64x32
constexpr int BKc    = 32;
constexpr int PITCH  = 144;                // 32 fp32 (128B) padded to 144B
constexpr int MATB   = 128 * PITCH;        // 18432
constexpr int STAGEB = 2 * MATB;           // A + B = 36864
constexpr int NSTAGE = 3;                  // triple buffered
constexpr int SMEM_DYN = NSTAGE * STAGEB;  // 110592; 2 CTAs = 216KB < 228KB

// ---------------------------------------------------------------------------
// Scratch (static device globals — no runtime allocation allowed)
// ---------------------------------------------------------------------------
__device__ __align__(256) float g_X [(size_t)cM * cD];
__device__ __align__(256) float g_Wq[(size_t)cD * cD];
__device__ __align__(256) float g_Wk[(size_t)cD * cD];
__device__ __align__(256) float g_Wv[(size_t)cD * cD];
__device__ __align__(256) float g_Q [(size_t)cM * cD];
__device__ __align__(256) float g_K [(size_t)cM * cD];
__device__ __align__(256) float g_V [(size_t)cM * cD];
__device__ __align__(256) float g_Vt[(size_t)cB * cD * cT];  // [B, D, T]
__device__ __align__(256) float g_S [(size_t)cB * cT * cT];  // scores, then P in place

// ---------------------------------------------------------------------------
// PTX helpers (family-portable: cp.async, ldmatrix, mma.sync tf32)
// ---------------------------------------------------------------------------
__device__ __forceinline__ uint32_t smem_u32(const void* p) {
    uint32_t a;
    asm("{ .reg .u64 t; cvta.to.shared.u64 t, %1; cvt.u32.u64 %0, t; }"
        : "=r"(a) : "l"(p));
    return a;
}

__device__ __forceinline__ void cp_async16(uint32_t dst, const void* src) {
    asm volatile("cp.async.cg.shared.global [%0], [%1], 16;"
                 :: "r"(dst), "l"(src) : "memory");
}
__device__ __forceinline__ void cp_commit() {
    asm volatile("cp.async.commit_group;" ::: "memory");
}
template <int N>
__device__ __forceinline__ void cp_wait() {
    asm volatile("cp.async.wait_group %0;" :: "n"(N) : "memory");
}

__device__ __forceinline__ void ldsm_x4(uint32_t* r, uint32_t addr) {
    asm volatile("ldmatrix.sync.aligned.m8n8.x4.shared.b16 {%0,%1,%2,%3}, [%4];"
                 : "=r"(r[0]), "=r"(r[1]), "=r"(r[2]), "=r"(r[3]) : "r"(addr));
}

__device__ __forceinline__ void mma_tf32(float* c, const uint32_t* a, const uint32_t* b) {
    asm volatile(
        "mma.sync.aligned.m16n8k8.row.col.f32.tf32.tf32.f32 "
        "{%0,%1,%2,%3}, {%4,%5,%6,%7}, {%8,%9}, {%0,%1,%2,%3};"
        : "+f"(c[0]), "+f"(c[1]), "+f"(c[2]), "+f"(c[3])
        : "r"(a[0]), "r"(a[1]), "r"(a[2]), "r"(a[3]), "r"(b[0]), "r"(b[1]));
}

// Round-to-nearest tf32 (unbiased — truncation would bias dot products ~1e-3)
__device__ __forceinline__ float to_tf32(float x) {
    uint32_t r;
    asm("cvt.rna.tf32.f32 %0, %1;" : "=r"(r) : "f"(x));
    return __uint_as_float(r);
}

// ---------------------------------------------------------------------------
// Core: 128x128 output tile, C = A * B^T, fp32 operands pre-rounded to tf32.
// A: rows m0..m0+127 of [.., lda]; B: rows n0..n0+127 of [.., lda]; K = kIters*32.
// 3-stage cp.async pipeline, ONE __syncthreads per k-step.
// Group accounting: exactly one commit per iteration (empty on tail), so at the
// top of iter kt the FIFO guarantees "<=1 pending" == "stage kt resident".
// Requires kIters >= 2 (always true here: min is 4).
// ROUND: apply tf32 rounding to C on store (for Q/K/V feeding later GEMMs).
// ---------------------------------------------------------------------------
template <int ROUND>
__device__ __forceinline__ void gemm128_tf32(
    const float* __restrict__ A, const float* __restrict__ B,
    int lda, int kIters, int m0, int n0,
    float* __restrict__ C, int ldc)
{
    extern __shared__ char smem[];
    const int tid  = threadIdx.x;
    const int wid  = tid >> 5;
    const int lane = tid & 31;
    const int wm   = (wid & 1) * 64;   // warp tile m-origin
    const int wn   = (wid >> 1) * 32;  // warp tile n-origin
    const uint32_t sbase = smem_u32(smem);

    float acc[4][4][4];
#pragma unroll
    for (int i = 0; i < 4; i++)
#pragma unroll
        for (int j = 0; j < 4; j++)
#pragma unroll
            for (int r = 0; r < 4; r++) acc[i][j][r] = 0.0f;

    // ---- async stage loader: 2 mats x 128 rows x 8 x 16B chunks = 2048
    auto load_stage = [&](int s) {
        const int k0 = s * BKc;
        const uint32_t dst0 = sbase + (uint32_t)((s % NSTAGE) * STAGEB);
#pragma unroll
        for (int i = 0; i < 8; i++) {
            const int c   = tid + i * 256;   // 0..2047
            const int mat = c >> 10;
            const int cc  = c & 1023;
            const int row = cc >> 3;
            const int seg = cc & 7;
            const float* src = mat ? B : A;
            const int r0 = mat ? n0 : m0;
            cp_async16(dst0 + (uint32_t)(mat * MATB + row * PITCH + seg * 16),
                       src + (size_t)(r0 + row) * lda + k0 + seg * 4);
        }
        cp_commit();
    };

    // Prime two stages
    load_stage(0);
    load_stage(1);

    // ldmatrix lane->address: quad q selects (row+8?, col+4?) sub-tile
    const int q  = lane >> 3;
    const int r8 = lane & 7;
    const uint32_t a_off = (uint32_t)((wm + (q & 1) * 8 + r8) * PITCH + (q >> 1) * 16);
    const uint32_t b_off = (uint32_t)((wn + (q & 1) * 8 + r8) * PITCH + (q >> 1) * 16)
                           + (uint32_t)MATB;

    for (int kt = 0; kt < kIters; kt++) {
        // Stage kt resident when <=1 newer group pending (FIFO completion).
        cp_wait<1>();
        __syncthreads();   // all warps done reading buffer (kt-1)%3 == (kt+2)%3

        if (kt + 2 < kIters) load_stage(kt + 2);
        else                 cp_commit();          // empty group keeps FIFO count

        const uint32_t sb = sbase + (uint32_t)((kt % NSTAGE) * STAGEB);
#pragma unroll
        for (int kh = 0; kh < 4; kh++) {           // 4 x k8 per stage
            uint32_t a[4][4], b[4][2];
#pragma unroll
            for (int mt = 0; mt < 4; mt++)
                ldsm_x4(a[mt], sb + a_off + (uint32_t)(mt * 16 * PITCH + kh * 32));
#pragma unroll
            for (int np = 0; np < 2; np++) {
                uint32_t t[4];
                ldsm_x4(t, sb + b_off + (uint32_t)(np * 16 * PITCH + kh * 32));
                b[2 * np + 0][0] = t[0]; b[2 * np + 1][0] = t[1];
                b[2 * np + 0][1] = t[2]; b[2 * np + 1][1] = t[3];
            }
#pragma unroll
            for (int mt = 0; mt < 4; mt++)
#pragma unroll
                for (int nt = 0; nt < 4; nt++)
                    mma_tf32(acc[mt][nt], a[mt], b[nt]);
        }
        // no trailing barrier: next iteration's top barrier protects reuse
    }

    // ---- epilogue ----
    const int er = lane >> 2;          // 0..7
    const int ec = (lane & 3) * 2;     // 0,2,4,6
#pragma unroll
    for (int mt = 0; mt < 4; mt++) {
#pragma unroll
        for (int half = 0; half < 2; half++) {
            const int gr = m0 + wm + mt * 16 + er + half * 8;
#pragma unroll
            for (int nt = 0; nt < 4; nt++) {
                float v0 = acc[mt][nt][half * 2 + 0];
                float v1 = acc[mt][nt][half * 2 + 1];
                if (ROUND) { v0 = to_tf32(v0); v1 = to_tf32(v1); }
                const int gc = n0 + wn + nt * 8 + ec;
                *(float2*)(C + (size_t)gr * ldc + gc) = make_float2(v0, v1);
            }
        }
    }
}

// ---------------------------------------------------------------------------
// Kernels
// ---------------------------------------------------------------------------
// Single launch rounds all four inputs to tf32 (rna).
// Block map: [0, 8192) -> X ; then 1024 blocks each for Wq, Wk, Wv.
__global__ void round_all_kernel(const float* __restrict__ X,
                                 const float* __restrict__ Wq,
                                 const float* __restrict__ Wk,
                                 const float* __restrict__ Wv)
{
    const int b = blockIdx.x;
    const float* src;
    float* dst;
    int rel;
    if (b < 8192)      { src = X;  dst = g_X;  rel = b; }
    else if (b < 9216) { src = Wq; dst = g_Wq; rel = b - 8192; }
    else if (b < 10240){ src = Wk; dst = g_Wk; rel = b - 9216; }
    else               { src = Wv; dst = g_Wv; rel = b - 10240; }
    const int i = (rel * 256 + threadIdx.x) * 4;
    float4 v = *(const float4*)(src + i);
    v.x = to_tf32(v.x); v.y = to_tf32(v.y);
    v.z = to_tf32(v.z); v.w = to_tf32(v.w);
    *(float4*)(dst + i) = v;
}

__global__ __launch_bounds__(256, 2) void qkv_gemm_kernel()
{
    const int z = blockIdx.z;
    const float* W;
    float* C;
    if (z == 0)      { W = g_Wq; C = g_Q; }
    else if (z == 1) { W = g_Wk; C = g_K; }
    else             { W = g_Wv; C = g_V; }
    gemm128_tf32<1>(g_X, W, cD, cD / BKc,
                    blockIdx.y * 128, blockIdx.x * 128, C, cD);
}

// V [T, D] -> Vt [D, T] per batch (already tf32-rounded values)
__global__ void transpose_kernel()
{
    __shared__ float t[32][33];
    const int b = blockIdx.z;
    const float* in = g_V + (size_t)b * cT * cD;
    float* out      = g_Vt + (size_t)b * cD * cT;
    const int d0 = blockIdx.x * 32;
    const int t0 = blockIdx.y * 32;
    const int tx = threadIdx.x, ty = threadIdx.y;  // 32 x 8
#pragma unroll
    for (int j = 0; j < 32; j += 8)
        t[ty + j][tx] = in[(size_t)(t0 + ty + j) * cD + d0 + tx];
    __syncthreads();
#pragma unroll
    for (int j = 0; j < 32; j += 8)
        out[(size_t)(d0 + ty + j) * cT + t0 + tx] = t[tx][ty + j];
}

__global__ __launch_bounds__(256, 2) void scores_gemm_kernel()
{
    const int b  = blockIdx.z;
    const int m0 = blockIdx.y * 128;
    const int n0 = blockIdx.x * 128;
    if (n0 > m0) return;  // tile fully above causal diagonal
    const size_t off = (size_t)b * cT * cD;
    gemm128_tf32<0>(g_Q + off, g_K + off, cD, cD / BKc, m0, n0,
                    g_S + (size_t)b * cT * cT, cT);
}

// softmax row in place -> tf32-rounded P, zero-filled to the row's 128 boundary
__global__ __launch_bounds__(256) void softmax_kernel()
{
    const int q   = blockIdx.x;
    const int b   = blockIdx.y;
    const int tid = threadIdx.x;
    float* row    = g_S + (size_t)b * cT * cT + (size_t)q * cT;
    const int len = q + 1;

    __shared__ float red[256];

    float m = -1e30f;
    for (int i = tid; i < len; i += 256) m = fmaxf(m, row[i]);
    red[tid] = m;
    __syncthreads();
    for (int s = 128; s > 0; s >>= 1) {
        if (tid < s) red[tid] = fmaxf(red[tid], red[tid + s]);
        __syncthreads();
    }
    m = red[0];
    __syncthreads();

    const float scale = 0.03125f;  // 1/sqrt(1024)
    float sum = 0.0f;
    for (int i = tid; i < len; i += 256) {
        float e = __expf((row[i] - m) * scale);
        row[i] = e;
        sum += e;
    }
    red[tid] = sum;
    __syncthreads();
    for (int s = 128; s > 0; s >>= 1) {
        if (tid < s) red[tid] += red[tid + s];
        __syncthreads();
    }
    const float inv = 1.0f / red[0];
    __syncthreads();

    for (int i = tid; i < len; i += 256)
        row[i] = to_tf32(row[i] * inv);

    const int end = ((q >> 7) + 1) << 7;
    for (int i = len + tid; i < end; i += 256) row[i] = 0.0f;
}

__global__ __launch_bounds__(256, 2) void pv_gemm_kernel(float* __restrict__ out)
{
    const int b  = blockIdx.z;
    const int m0 = blockIdx.y * 128;
    const int n0 = blockIdx.x * 128;
    const int kIters = (m0 + 128) / BKc;   // causal truncation (min 4)
    gemm128_tf32<0>(g_S + (size_t)b * cT * cT, g_Vt + (size_t)b * cD * cT,
                    cT, kIters, m0, n0,
                    out + (size_t)b * cT * cD, cD);
}

// ---------------------------------------------------------------------------
extern "C" void kernel_launch(void* const* d_in, const int* in_sizes, int n_in,
                              void* d_out, int out_size)
{
    const float* X  = (const float*)d_in[0];
    const float* Wq = (const float*)d_in[1];
    const float* Wk = (const float*)d_in[2];
    const float* Wv = (const float*)d_in[3];
    float* out      = (float*)d_out;

    cudaFuncSetAttribute(qkv_gemm_kernel,    cudaFuncAttributeMaxDynamicSharedMemorySize, SMEM_DYN);
    cudaFuncSetAttribute(scores_gemm_kernel, cudaFuncAttributeMaxDynamicSharedMemorySize, SMEM_DYN);
    cudaFuncSetAttribute(pv_gemm_kernel,     cudaFuncAttributeMaxDynamicSharedMemorySize, SMEM_DYN);

    // 1) round all inputs to tf32 (one launch)
    round_all_kernel<<<8192 + 3 * 1024, 256>>>(X, Wq, Wk, Wv);

    // 2) QKV projections (tf32 HMMA), outputs tf32-rounded
    qkv_gemm_kernel<<<dim3(cD / 128, cM / 128, 3), 256, SMEM_DYN>>>();

    // 3) V -> V^T per batch
    transpose_kernel<<<dim3(cD / 32, cT / 32, cB), dim3(32, 8)>>>();

    // 4) S = Q K^T, causal tiles only
    scores_gemm_kernel<<<dim3(cT / 128, cT / 128, cB), 256, SMEM_DYN>>>();

    // 5) softmax in place -> tf32-rounded P (tail-zeroed)
    softmax_kernel<<<dim3(cT, cB), 256>>>();

    // 6) O = P V
    pv_gemm_kernel<<<dim3(cD / 128, cT / 128, cB), 256, SMEM_DYN>>>(out);
}